// round 4
// baseline (speedup 1.0000x reference)
#include <cuda_runtime.h>
#include <math.h>

// ---------------- problem constants ----------------
#define NB   16
#define DIM  64
#define DLEN 64
#define PLEN 1200
#define D1L  61
#define D2L  56
#define D3L  49
#define P1L  1197
#define P2L  1190
#define P3L  1179
#define C1   40
#define C2   80
#define C3   160

typedef unsigned long long u64;

// ---------------- scratch (device globals; no allocs allowed) ----------------
__device__ float g_d1[NB * C1 * D1L];
__device__ float g_d2[NB * C2 * D2L];
__device__ float g_dc[NB * C3 * D3L];
__device__ float g_p1[NB * C1 * P1L];
__device__ float g_p2[NB * C2 * P2L];
__device__ float g_pc[NB * C3 * P3L];
__device__ float g_datt[NB * C3 * D3L];
__device__ float g_patt[NB * C3 * P3L];
__device__ float g_Sd[NB * C3 * D3L];
__device__ float g_Sp[NB * C3 * P3L];
__device__ float g_catte[NB * C3 * D3L];
__device__ float g_patte[NB * C3 * P3L];
__device__ float g_pair[NB * 320];

// ---------------- f32x2 packed helpers ----------------
__device__ __forceinline__ u64 pack2(float lo, float hi) {
    u64 d;
    asm("mov.b64 %0, {%1, %2};" : "=l"(d) : "r"(__float_as_uint(lo)), "r"(__float_as_uint(hi)));
    return d;
}
__device__ __forceinline__ void unpack2(float& lo, float& hi, u64 v) {
    unsigned int a, b;
    asm("mov.b64 {%0, %1}, %2;" : "=r"(a), "=r"(b) : "l"(v));
    lo = __uint_as_float(a); hi = __uint_as_float(b);
}
__device__ __forceinline__ void fma2(u64& d, u64 a, u64 b) {
    asm("fma.rn.f32x2 %0, %1, %2, %3;" : "=l"(d) : "l"(a), "l"(b), "l"(d));
}

// ---------------- generic tiled conv / K=1 GEMM kernel ----------------
// out[b][o][l] = epi( bias[o] + sum_{i,k} in[b][i][l+k] * W[o][i*K+k] )
// EPI: 0 relu, 1 linear, 2 sigmoid(scale*acc + bias)
// EMB: input gather = emb[tok[b][l+k]][i]  (CIN must be 64)
// Thread tile: OTT outputs x 4 positions, o packed as OTT/2 f32x2 accumulators.
template <int K, int CIN, int CH, int TILE_L, int TILE_O, int OTT, int EPI, int EMB>
__global__ void __launch_bounds__((TILE_L / 4) * (TILE_O / OTT))
conv_t(const float* __restrict__ in, const int* __restrict__ tok,
       const float* __restrict__ W, const float* __restrict__ bias,
       float* __restrict__ out, int Lin, int Lout, int Cout, float scale)
{
    constexpr int LT    = TILE_L / 4;
    constexpr int OT    = TILE_O / OTT;
    constexpr int NACC  = OTT / 2;
    constexpr int NTHR  = LT * OT;
    constexpr int NW4   = (K + 6) / 4;
    constexpr int PITCH = TILE_L + 4 * NW4;
    constexpr int WV    = TILE_L + K - 1;

    __shared__ float inS[CH * PITCH];
    __shared__ float wS[CH * K * TILE_O];
    __shared__ int tokS[EMB ? (TILE_L + 32) : 1];

    const int b  = blockIdx.z;
    const int o0 = blockIdx.y * TILE_O;
    const int l0 = blockIdx.x * TILE_L;
    const int tid = threadIdx.x;
    const int lx = tid % LT, oy = tid / LT;
    const int lbase = lx * 4;

    if (EMB) {
        for (int idx = tid; idx < WV; idx += NTHR) {
            int gl = l0 + idx;
            tokS[idx] = (gl < Lin) ? tok[b * Lin + gl] : 0;
        }
    }

    u64 accp[NACC][4];
#pragma unroll
    for (int p = 0; p < NACC; p++)
#pragma unroll
        for (int t = 0; t < 4; t++) {
            if (EPI == 2) accp[p][t] = 0ull;
            else accp[p][t] = pack2(bias[o0 + oy * OTT + 2 * p], bias[o0 + oy * OTT + 2 * p + 1]);
        }

    for (int ci0 = 0; ci0 < CIN; ci0 += CH) {
        __syncthreads();
        // stage input slab [CH][WV]
        for (int idx = tid; idx < CH * WV; idx += NTHR) {
            int i2 = idx / WV, j = idx - i2 * WV;
            int gl = l0 + j;
            float v;
            if (EMB)
                v = (gl < Lin) ? in[tokS[j] * 64 + (ci0 + i2)] : 0.f;
            else
                v = (gl < Lin) ? in[((size_t)b * CIN + (ci0 + i2)) * Lin + gl] : 0.f;
            inS[i2 * PITCH + j] = v;
        }
        // stage weights: wS[(i2*K + k)*TILE_O + oo]
        for (int idx = tid; idx < CH * K * TILE_O; idx += NTHR) {
            int oo = idx % TILE_O, rest = idx / TILE_O;
            int i2 = rest / K, k = rest - i2 * K;
            wS[idx] = W[((size_t)(o0 + oo) * CIN + (ci0 + i2)) * K + k];
        }
        __syncthreads();

#pragma unroll 2
        for (int i2 = 0; i2 < CH; i2++) {
            float win[NW4 * 4];
#pragma unroll
            for (int n = 0; n < NW4; n++) {
                float4 v = *(const float4*)&inS[i2 * PITCH + lbase + 4 * n];
                win[4 * n + 0] = v.x; win[4 * n + 1] = v.y;
                win[4 * n + 2] = v.z; win[4 * n + 3] = v.w;
            }
            u64 wdup[K + 3];
#pragma unroll
            for (int j = 0; j < K + 3; j++) wdup[j] = pack2(win[j], win[j]);
#pragma unroll
            for (int k = 0; k < K; k++) {
                const u64* wrow = (const u64*)&wS[(i2 * K + k) * TILE_O + oy * OTT];
                u64 wp[NACC];
#pragma unroll
                for (int p = 0; p < NACC; p++) wp[p] = wrow[p];
#pragma unroll
                for (int t = 0; t < 4; t++)
#pragma unroll
                    for (int p = 0; p < NACC; p++)
                        fma2(accp[p][t], wp[p], wdup[k + t]);
            }
        }
    }

#pragma unroll
    for (int p = 0; p < NACC; p++) {
        int olo = o0 + oy * OTT + 2 * p;
#pragma unroll
        for (int t = 0; t < 4; t++) {
            int l = l0 + lbase + t;
            if (l >= Lout) continue;
            float vlo, vhi;
            unpack2(vlo, vhi, accp[p][t]);
            if (EPI == 0) { vlo = fmaxf(vlo, 0.f); vhi = fmaxf(vhi, 0.f); }
            else if (EPI == 2) {
                vlo = 1.f / (1.f + __expf(-(vlo * scale + bias[olo])));
                vhi = 1.f / (1.f + __expf(-(vhi * scale + bias[olo + 1])));
            }
            out[((size_t)b * Cout + olo) * Lout + l] = vlo;
            out[((size_t)b * Cout + olo + 1) * Lout + l] = vhi;
        }
    }
}

// ---------------- interaction sums ----------------
__global__ void interact_kernel(const float* __restrict__ datt, const float* __restrict__ patt,
                                float* __restrict__ Sd, float* __restrict__ Sp)
{
    int k = blockIdx.x, b = blockIdx.y;
    int t = threadIdx.x;
    __shared__ float dvs[D3L];
    __shared__ float red[8][D3L];

    const float* dv = datt + ((size_t)b * C3 + k) * D3L;
    const float* pv = patt + ((size_t)b * C3 + k) * P3L;
    float* SpRow = Sp + ((size_t)b * C3 + k) * P3L;

    if (t < D3L) dvs[t] = dv[t];
    __syncthreads();

    float dl[D3L];
#pragma unroll
    for (int d = 0; d < D3L; d++) dl[d] = dvs[d];
    float sdp[D3L];
#pragma unroll
    for (int d = 0; d < D3L; d++) sdp[d] = 0.f;

    for (int p = t; p < P3L; p += 256) {
        float pvv = pv[p];
        float sp = 0.f;
#pragma unroll
        for (int d = 0; d < D3L; d++) {
            float v = fmaxf(dl[d] + pvv, 0.f);
            sdp[d] += v;
            sp += v;
        }
        SpRow[p] = sp;
    }

    int warp = t >> 5, lane = t & 31;
#pragma unroll
    for (int d = 0; d < D3L; d++) {
        float v = sdp[d];
        v += __shfl_xor_sync(0xffffffffu, v, 16);
        v += __shfl_xor_sync(0xffffffffu, v, 8);
        v += __shfl_xor_sync(0xffffffffu, v, 4);
        v += __shfl_xor_sync(0xffffffffu, v, 2);
        v += __shfl_xor_sync(0xffffffffu, v, 1);
        if (lane == 0) red[warp][d] = v;
    }
    __syncthreads();
    if (t < D3L) {
        float s = 0.f;
#pragma unroll
        for (int w = 0; w < 8; w++) s += red[w][t];
        Sd[((size_t)b * C3 + k) * D3L + t] = s;
    }
}

// ---------------- gated max pool ----------------
__global__ void pool_kernel(const float* __restrict__ x, const float* __restrict__ att,
                            float* __restrict__ pairv, int L, int off)
{
    int k = blockIdx.x, b = blockIdx.y;
    const float* xr = x + ((size_t)b * C3 + k) * L;
    const float* ar = att + ((size_t)b * C3 + k) * L;
    float m = -1e30f;
    for (int l = threadIdx.x; l < L; l += 32)
        m = fmaxf(m, xr[l] * (0.5f + ar[l]));
#pragma unroll
    for (int s = 16; s; s >>= 1)
        m = fmaxf(m, __shfl_xor_sync(0xffffffffu, m, s));
    if (threadIdx.x == 0) pairv[b * 320 + off + k] = m;
}

// ---------------- fused 4-layer MLP head (one block per batch row) ----------------
__global__ void __launch_bounds__(1024)
mlp_kernel(const float* __restrict__ pairv,
           const float* __restrict__ fc1W, const float* __restrict__ fc1b,
           const float* __restrict__ fc2W, const float* __restrict__ fc2b,
           const float* __restrict__ fc3W, const float* __restrict__ fc3b,
           const float* __restrict__ outW, const float* __restrict__ outb,
           float* __restrict__ out)
{
    __shared__ float s0[320];
    __shared__ float h1s[1024];
    __shared__ float h2s[1024];
    __shared__ float h3s[512];
    int b = blockIdx.x, t = threadIdx.x;

    if (t < 320) s0[t] = pairv[b * 320 + t];
    __syncthreads();

    // fc1: 320 -> 1024
    {
        const float4* Wo = (const float4*)(fc1W + (size_t)t * 320);
        float acc = fc1b[t];
#pragma unroll 8
        for (int i = 0; i < 80; i++) {
            float4 wv = Wo[i];
            const float* xv = &s0[4 * i];
            acc = fmaf(wv.x, xv[0], acc);
            acc = fmaf(wv.y, xv[1], acc);
            acc = fmaf(wv.z, xv[2], acc);
            acc = fmaf(wv.w, xv[3], acc);
        }
        h1s[t] = acc > 0.f ? acc : 0.01f * acc;
    }
    __syncthreads();

    // fc2: 1024 -> 1024
    {
        const float4* Wo = (const float4*)(fc2W + (size_t)t * 1024);
        float acc = fc2b[t];
#pragma unroll 8
        for (int i = 0; i < 256; i++) {
            float4 wv = Wo[i];
            const float* xv = &h1s[4 * i];
            acc = fmaf(wv.x, xv[0], acc);
            acc = fmaf(wv.y, xv[1], acc);
            acc = fmaf(wv.z, xv[2], acc);
            acc = fmaf(wv.w, xv[3], acc);
        }
        h2s[t] = acc > 0.f ? acc : 0.01f * acc;
    }
    __syncthreads();

    // fc3: 1024 -> 512
    if (t < 512) {
        const float4* Wo = (const float4*)(fc3W + (size_t)t * 1024);
        float acc = fc3b[t];
#pragma unroll 8
        for (int i = 0; i < 256; i++) {
            float4 wv = Wo[i];
            const float* xv = &h2s[4 * i];
            acc = fmaf(wv.x, xv[0], acc);
            acc = fmaf(wv.y, xv[1], acc);
            acc = fmaf(wv.z, xv[2], acc);
            acc = fmaf(wv.w, xv[3], acc);
        }
        h3s[t] = acc > 0.f ? acc : 0.01f * acc;
    }
    __syncthreads();

    // out: 512 -> 2 (32 lanes per output)
    if (t < 64) {
        int o = t >> 5, lane = t & 31;
        const float* Wo = outW + (size_t)o * 512;
        float acc = 0.f;
#pragma unroll
        for (int i = 0; i < 16; i++)
            acc = fmaf(Wo[lane + 32 * i], h3s[lane + 32 * i], acc);
#pragma unroll
        for (int s = 16; s; s >>= 1)
            acc += __shfl_xor_sync(0xffffffffu, acc, s);
        if (lane == 0) out[b * 2 + o] = acc + outb[o];
    }
}

// ---------------- launch (single default stream; no streams/events/statics) ----------------
extern "C" void kernel_launch(void* const* d_in, const int* in_sizes, int n_in,
                              void* d_out, int out_size)
{
    const int*   dtok = (const int*)d_in[0];
    const int*   ptok = (const int*)d_in[1];
    const float* demb = (const float*)d_in[2];
    const float* pemb = (const float*)d_in[3];
    const float* dW1 = (const float*)d_in[4],  *db1 = (const float*)d_in[5];
    const float* dW2 = (const float*)d_in[6],  *db2 = (const float*)d_in[7];
    const float* dW3 = (const float*)d_in[8],  *db3 = (const float*)d_in[9];
    const float* pW1 = (const float*)d_in[10], *pb1 = (const float*)d_in[11];
    const float* pW2 = (const float*)d_in[12], *pb2 = (const float*)d_in[13];
    const float* pW3 = (const float*)d_in[14], *pb3 = (const float*)d_in[15];
    const float* dattW = (const float*)d_in[16], *dattb = (const float*)d_in[17];
    const float* pattW = (const float*)d_in[18], *pattb = (const float*)d_in[19];
    const float* attW  = (const float*)d_in[20], *attb  = (const float*)d_in[21];
    const float* fc1W = (const float*)d_in[22], *fc1b = (const float*)d_in[23];
    const float* fc2W = (const float*)d_in[24], *fc2b = (const float*)d_in[25];
    const float* fc3W = (const float*)d_in[26], *fc3b = (const float*)d_in[27];
    const float* outW = (const float*)d_in[28], *outb = (const float*)d_in[29];
    float* out = (float*)d_out;

    float *d1, *d2, *dc, *p1, *p2, *pc;
    float *datt, *patt, *Sd, *Sp, *catte, *patte, *pairv;
    cudaGetSymbolAddress((void**)&d1, g_d1);
    cudaGetSymbolAddress((void**)&d2, g_d2);
    cudaGetSymbolAddress((void**)&dc, g_dc);
    cudaGetSymbolAddress((void**)&p1, g_p1);
    cudaGetSymbolAddress((void**)&p2, g_p2);
    cudaGetSymbolAddress((void**)&pc, g_pc);
    cudaGetSymbolAddress((void**)&datt, g_datt);
    cudaGetSymbolAddress((void**)&patt, g_patt);
    cudaGetSymbolAddress((void**)&Sd, g_Sd);
    cudaGetSymbolAddress((void**)&Sp, g_Sp);
    cudaGetSymbolAddress((void**)&catte, g_catte);
    cudaGetSymbolAddress((void**)&patte, g_patte);
    cudaGetSymbolAddress((void**)&pairv, g_pair);

    // ---- drug branch (embedding fused into conv1) ----
    conv_t<4, 64, 16, 64, 8, 4, 0, 1><<<dim3(1, C1 / 8, NB), 32>>>(
        demb, dtok, dW1, db1, d1, DLEN, D1L, C1, 0.f);
    conv_t<6, 40, 20, 64, 16, 4, 0, 0><<<dim3(1, C2 / 16, NB), 64>>>(
        d1, 0, dW2, db2, d2, D1L, D2L, C2, 0.f);
    conv_t<8, 80, 16, 64, 16, 4, 0, 0><<<dim3(1, C3 / 16, NB), 64>>>(
        d2, 0, dW3, db3, dc, D2L, D3L, C3, 0.f);
    conv_t<1, 160, 32, 64, 16, 4, 1, 0><<<dim3(1, C3 / 16, NB), 64>>>(
        dc, 0, dattW, dattb, datt, D3L, D3L, C3, 0.f);

    // ---- protein branch (embedding fused into conv1; OTT=8 on big kernels) ----
    conv_t<4, 64, 16, 256, 8, 4, 0, 1><<<dim3(5, C1 / 8, NB), 128>>>(
        pemb, ptok, pW1, pb1, p1, PLEN, P1L, C1, 0.f);
    conv_t<8, 40, 20, 256, 16, 4, 0, 0><<<dim3(5, C2 / 16, NB), 256>>>(
        p1, 0, pW2, pb2, p2, P1L, P2L, C2, 0.f);
    conv_t<12, 80, 16, 256, 32, 8, 0, 0><<<dim3(5, C3 / 32, NB), 256>>>(
        p2, 0, pW3, pb3, pc, P2L, P3L, C3, 0.f);
    conv_t<1, 160, 32, 256, 32, 8, 1, 0><<<dim3(5, C3 / 32, NB), 256>>>(
        pc, 0, pattW, pattb, patt, P3L, P3L, C3, 0.f);

    // ---- interaction ----
    interact_kernel<<<dim3(C3, NB), 256>>>(datt, patt, Sd, Sp);

    // ---- attention outputs + pools ----
    conv_t<1, 160, 32, 64, 16, 4, 2, 0><<<dim3(1, C3 / 16, NB), 64>>>(
        Sd, 0, attW, attb, catte, D3L, D3L, C3, 1.f / (float)P3L);
    pool_kernel<<<dim3(C3, NB), 32>>>(dc, catte, pairv, D3L, 0);

    conv_t<1, 160, 32, 256, 32, 8, 2, 0><<<dim3(5, C3 / 32, NB), 256>>>(
        Sp, 0, attW, attb, patte, P3L, P3L, C3, 1.f / (float)D3L);
    pool_kernel<<<dim3(C3, NB), 32>>>(pc, patte, pairv, P3L, 160);

    // ---- MLP head ----
    mlp_kernel<<<NB, 1024>>>(pairv, fc1W, fc1b, fc2W, fc2b, fc3W, fc3b, outW, outb, out);
}

// round 7
// speedup vs baseline: 1.0547x; 1.0547x over previous
#include <cuda_runtime.h>
#include <math.h>

// ---------------- problem constants ----------------
#define NB   16
#define DLEN 64
#define PLEN 1200
#define D1L  61
#define D2L  56
#define D3L  49
#define P1L  1197
#define P2L  1190
#define P3L  1179
#define C1   40
#define C2   80
#define C3   160

typedef unsigned long long u64;

// ---------------- scratch (device globals; no allocs allowed) ----------------
__device__ float g_d1[NB * C1 * D1L];
__device__ float g_d2[NB * C2 * D2L];
__device__ float g_dc[NB * C3 * D3L];
__device__ float g_p1[NB * C1 * P1L];
__device__ float g_p2[NB * C2 * P2L];
__device__ float g_pc[NB * C3 * P3L];
__device__ float g_datt[NB * C3 * D3L];
__device__ float g_patt[NB * C3 * P3L];
__device__ float g_Sd[NB * C3 * D3L];
__device__ float g_Sp[NB * C3 * P3L];
__device__ float g_catte[NB * C3 * D3L];
__device__ float g_patte[NB * C3 * P3L];
__device__ float g_pair[NB * 320];

// ---------------- f32x2 packed helpers ----------------
__device__ __forceinline__ u64 pack2(float lo, float hi) {
    u64 d;
    asm("mov.b64 %0, {%1, %2};" : "=l"(d) : "r"(__float_as_uint(lo)), "r"(__float_as_uint(hi)));
    return d;
}
__device__ __forceinline__ void unpack2(float& lo, float& hi, u64 v) {
    unsigned int a, b;
    asm("mov.b64 {%0, %1}, %2;" : "=r"(a), "=r"(b) : "l"(v));
    lo = __uint_as_float(a); hi = __uint_as_float(b);
}
__device__ __forceinline__ void fma2(u64& d, u64 a, u64 b) {
    asm("fma.rn.f32x2 %0, %1, %2, %3;" : "=l"(d) : "l"(a), "l"(b), "l"(d));
}

// ---------------- conv config ----------------
template <int K_, int CIN_, int CH_, int TL_, int TO_, int OTT_, int EPI_, int EMB_>
struct CC {
    static constexpr int K = K_, CIN = CIN_, CH = CH_, TILE_L = TL_, TILE_O = TO_;
    static constexpr int OTT = OTT_, EPI = EPI_, EMB = EMB_;
    static constexpr int LT = TL_ / 4, OT = TO_ / OTT_, NACC = OTT_ / 2;
    static constexpr int NTHR = LT * OT;
    static constexpr int NW4 = (K_ + 6) / 4;
    static constexpr int PITCH = TL_ + 4 * NW4;
    static constexpr int WV = TL_ + K_ - 1;
    static constexpr int SMEMF = CH_ * PITCH + CH_ * K_ * TO_ + (EMB_ ? (TL_ + 32) : 0);
};

// ---------------- conv body (device function over shared buffer) ----------------
// out[b][o][l] = epi( bias[o] + sum_{i,k} in[b][i][l+k] * W[o][i*K+k] )
// EPI: 0 relu, 1 linear, 2 sigmoid(scale*acc + bias); EMB: in = emb[tok[l+k]][i]
template <class C>
__device__ __forceinline__ void conv_body(
    float* __restrict__ sm,
    const float* __restrict__ in, const int* __restrict__ tok,
    const float* __restrict__ W, const float* __restrict__ bias,
    float* __restrict__ out, int Lin, int Lout, int Cout, float scale,
    int bx, int by, int bz, int BT)
{
    constexpr int K = C::K, CIN = C::CIN, CH = C::CH;
    constexpr int TILE_L = C::TILE_L, TILE_O = C::TILE_O, OTT = C::OTT;
    constexpr int LT = C::LT, OT = C::OT, NACC = C::NACC, NTHR = C::NTHR;
    constexpr int NW4 = C::NW4, PITCH = C::PITCH, WV = C::WV;

    float* inS = sm;
    float* wS  = sm + CH * PITCH;
    int*  tokS = (int*)(wS + CH * K * TILE_O);

    const int b = bz, o0 = by * TILE_O, l0 = bx * TILE_L;
    const int tid = threadIdx.x;
    const int lx = tid % LT, oy = tid / LT;
    const int lbase = lx * 4;
    const bool act = tid < NTHR;

    if (C::EMB) {
        for (int idx = tid; idx < WV; idx += BT) {
            int gl = l0 + idx;
            tokS[idx] = (gl < Lin) ? tok[b * Lin + gl] : 0;
        }
    }

    u64 accp[NACC][4];
    if (act) {
#pragma unroll
        for (int p = 0; p < NACC; p++)
#pragma unroll
            for (int t = 0; t < 4; t++) {
                if (C::EPI == 2) accp[p][t] = 0ull;
                else accp[p][t] = pack2(bias[o0 + oy * OTT + 2 * p],
                                        bias[o0 + oy * OTT + 2 * p + 1]);
            }
    }

    for (int ci0 = 0; ci0 < CIN; ci0 += CH) {
        __syncthreads();
        for (int idx = tid; idx < CH * WV; idx += BT) {
            int i2 = idx / WV, j = idx - i2 * WV;
            int gl = l0 + j;
            float v;
            if (C::EMB)
                v = (gl < Lin) ? in[tokS[j] * 64 + (ci0 + i2)] : 0.f;
            else
                v = (gl < Lin) ? in[((size_t)b * CIN + (ci0 + i2)) * Lin + gl] : 0.f;
            inS[i2 * PITCH + j] = v;
        }
        for (int idx = tid; idx < CH * K * TILE_O; idx += BT) {
            int oo = idx % TILE_O, rest = idx / TILE_O;
            int i2 = rest / K, k = rest - i2 * K;
            wS[idx] = W[((size_t)(o0 + oo) * CIN + (ci0 + i2)) * K + k];
        }
        __syncthreads();

        if (act) {
#pragma unroll 2
            for (int i2 = 0; i2 < CH; i2++) {
                float win[NW4 * 4];
#pragma unroll
                for (int n = 0; n < NW4; n++) {
                    float4 v = *(const float4*)&inS[i2 * PITCH + lbase + 4 * n];
                    win[4 * n + 0] = v.x; win[4 * n + 1] = v.y;
                    win[4 * n + 2] = v.z; win[4 * n + 3] = v.w;
                }
                u64 wdup[K + 3];
#pragma unroll
                for (int j = 0; j < K + 3; j++) wdup[j] = pack2(win[j], win[j]);
#pragma unroll
                for (int k = 0; k < K; k++) {
                    const u64* wrow = (const u64*)&wS[(i2 * K + k) * TILE_O + oy * OTT];
                    u64 wp[NACC];
#pragma unroll
                    for (int p = 0; p < NACC; p++) wp[p] = wrow[p];
#pragma unroll
                    for (int t = 0; t < 4; t++)
#pragma unroll
                        for (int p = 0; p < NACC; p++)
                            fma2(accp[p][t], wp[p], wdup[k + t]);
                }
            }
        }
    }

    if (act) {
#pragma unroll
        for (int p = 0; p < NACC; p++) {
            int olo = o0 + oy * OTT + 2 * p;
#pragma unroll
            for (int t = 0; t < 4; t++) {
                int l = l0 + lbase + t;
                if (l >= Lout) continue;
                float vlo, vhi;
                unpack2(vlo, vhi, accp[p][t]);
                if (C::EPI == 0) { vlo = fmaxf(vlo, 0.f); vhi = fmaxf(vhi, 0.f); }
                else if (C::EPI == 2) {
                    vlo = 1.f / (1.f + __expf(-(vlo * scale + bias[olo])));
                    vhi = 1.f / (1.f + __expf(-(vhi * scale + bias[olo + 1])));
                }
                out[((size_t)b * Cout + olo) * Lout + l] = vlo;
                out[((size_t)b * Cout + olo + 1) * Lout + l] = vhi;
            }
        }
    }
}

// ---------------- dual conv kernel (protein blocks first, then drug blocks) ----------------
template <class CP, class CD>
__global__ void __launch_bounds__(256)
dual_conv(const float* __restrict__ inP, const int* __restrict__ tokP,
          const float* __restrict__ WP, const float* __restrict__ bP, float* __restrict__ outP,
          int LinP, int LoutP, float scP, int gxP, int gyP,
          const float* __restrict__ inD, const int* __restrict__ tokD,
          const float* __restrict__ WD, const float* __restrict__ bD, float* __restrict__ outD,
          int LinD, int LoutD, float scD, int gxD, int gyD)
{
    constexpr int SMF = CP::SMEMF > CD::SMEMF ? CP::SMEMF : CD::SMEMF;
    __shared__ __align__(16) float sm[SMF];
    int blk = blockIdx.x;
    int nP = gxP * gyP * NB;
    if (blk < nP) {
        int bx = blk % gxP; int r = blk / gxP;
        int by = r % gyP, bz = r / gyP;
        conv_body<CP>(sm, inP, tokP, WP, bP, outP, LinP, LoutP, gyP * CP::TILE_O,
                      scP, bx, by, bz, blockDim.x);
    } else {
        blk -= nP;
        int bx = blk % gxD; int r = blk / gxD;
        int by = r % gyD, bz = r / gyD;
        conv_body<CD>(sm, inD, tokD, WD, bD, outD, LinD, LoutD, gyD * CD::TILE_O,
                      scD, bx, by, bz, blockDim.x);
    }
}

// ---------------- interaction sums ----------------
__global__ void interact_kernel(const float* __restrict__ datt, const float* __restrict__ patt,
                                float* __restrict__ Sd, float* __restrict__ Sp)
{
    int k = blockIdx.x, b = blockIdx.y;
    int t = threadIdx.x;
    __shared__ float dvs[D3L];
    __shared__ float red[8][D3L];

    const float* dv = datt + ((size_t)b * C3 + k) * D3L;
    const float* pv = patt + ((size_t)b * C3 + k) * P3L;
    float* SpRow = Sp + ((size_t)b * C3 + k) * P3L;

    if (t < D3L) dvs[t] = dv[t];
    __syncthreads();

    float dl[D3L];
#pragma unroll
    for (int d = 0; d < D3L; d++) dl[d] = dvs[d];
    float sdp[D3L];
#pragma unroll
    for (int d = 0; d < D3L; d++) sdp[d] = 0.f;

    for (int p = t; p < P3L; p += 256) {
        float pvv = pv[p];
        float sp = 0.f;
#pragma unroll
        for (int d = 0; d < D3L; d++) {
            float v = fmaxf(dl[d] + pvv, 0.f);
            sdp[d] += v;
            sp += v;
        }
        SpRow[p] = sp;
    }

    int warp = t >> 5, lane = t & 31;
#pragma unroll
    for (int d = 0; d < D3L; d++) {
        float v = sdp[d];
        v += __shfl_xor_sync(0xffffffffu, v, 16);
        v += __shfl_xor_sync(0xffffffffu, v, 8);
        v += __shfl_xor_sync(0xffffffffu, v, 4);
        v += __shfl_xor_sync(0xffffffffu, v, 2);
        v += __shfl_xor_sync(0xffffffffu, v, 1);
        if (lane == 0) red[warp][d] = v;
    }
    __syncthreads();
    if (t < D3L) {
        float s = 0.f;
#pragma unroll
        for (int w = 0; w < 8; w++) s += red[w][t];
        Sd[((size_t)b * C3 + k) * D3L + t] = s;
    }
}

// ---------------- dual gated max pool ----------------
__global__ void pool_dual(const float* __restrict__ dc, const float* __restrict__ catte,
                          const float* __restrict__ pc, const float* __restrict__ patte,
                          float* __restrict__ pairv)
{
    int k = blockIdx.x, zy = blockIdx.y;
    const float* xr; const float* ar; int L, off, b;
    if (zy < NB) { b = zy; xr = dc; ar = catte; L = D3L; off = 0; }
    else         { b = zy - NB; xr = pc; ar = patte; L = P3L; off = 160; }
    xr += ((size_t)b * C3 + k) * L;
    ar += ((size_t)b * C3 + k) * L;
    float m = -1e30f;
    for (int l = threadIdx.x; l < L; l += 32)
        m = fmaxf(m, xr[l] * (0.5f + ar[l]));
#pragma unroll
    for (int s = 16; s; s >>= 1)
        m = fmaxf(m, __shfl_xor_sync(0xffffffffu, m, s));
    if (threadIdx.x == 0) pairv[b * 320 + off + k] = m;
}

// ---------------- fused 4-layer MLP head ----------------
__global__ void __launch_bounds__(1024)
mlp_kernel(const float* __restrict__ pairv,
           const float* __restrict__ fc1W, const float* __restrict__ fc1b,
           const float* __restrict__ fc2W, const float* __restrict__ fc2b,
           const float* __restrict__ fc3W, const float* __restrict__ fc3b,
           const float* __restrict__ outW, const float* __restrict__ outb,
           float* __restrict__ out)
{
    __shared__ float s0[320];
    __shared__ float h1s[1024];
    __shared__ float h2s[1024];
    __shared__ float h3s[512];
    int b = blockIdx.x, t = threadIdx.x;

    if (t < 320) s0[t] = pairv[b * 320 + t];
    __syncthreads();

    {
        const float4* Wo = (const float4*)(fc1W + (size_t)t * 320);
        float acc = fc1b[t];
#pragma unroll 8
        for (int i = 0; i < 80; i++) {
            float4 wv = Wo[i];
            const float* xv = &s0[4 * i];
            acc = fmaf(wv.x, xv[0], acc);
            acc = fmaf(wv.y, xv[1], acc);
            acc = fmaf(wv.z, xv[2], acc);
            acc = fmaf(wv.w, xv[3], acc);
        }
        h1s[t] = acc > 0.f ? acc : 0.01f * acc;
    }
    __syncthreads();

    {
        const float4* Wo = (const float4*)(fc2W + (size_t)t * 1024);
        float acc = fc2b[t];
#pragma unroll 8
        for (int i = 0; i < 256; i++) {
            float4 wv = Wo[i];
            const float* xv = &h1s[4 * i];
            acc = fmaf(wv.x, xv[0], acc);
            acc = fmaf(wv.y, xv[1], acc);
            acc = fmaf(wv.z, xv[2], acc);
            acc = fmaf(wv.w, xv[3], acc);
        }
        h2s[t] = acc > 0.f ? acc : 0.01f * acc;
    }
    __syncthreads();

    if (t < 512) {
        const float4* Wo = (const float4*)(fc3W + (size_t)t * 1024);
        float acc = fc3b[t];
#pragma unroll 8
        for (int i = 0; i < 256; i++) {
            float4 wv = Wo[i];
            const float* xv = &h2s[4 * i];
            acc = fmaf(wv.x, xv[0], acc);
            acc = fmaf(wv.y, xv[1], acc);
            acc = fmaf(wv.z, xv[2], acc);
            acc = fmaf(wv.w, xv[3], acc);
        }
        h3s[t] = acc > 0.f ? acc : 0.01f * acc;
    }
    __syncthreads();

    if (t < 64) {
        int o = t >> 5, lane = t & 31;
        const float* Wo = outW + (size_t)o * 512;
        float acc = 0.f;
#pragma unroll
        for (int i = 0; i < 16; i++)
            acc = fmaf(Wo[lane + 32 * i], h3s[lane + 32 * i], acc);
#pragma unroll
        for (int s = 16; s; s >>= 1)
            acc += __shfl_xor_sync(0xffffffffu, acc, s);
        if (lane == 0) out[b * 2 + o] = acc + outb[o];
    }
}

// ---------------- configs ----------------
using CP1 = CC<4, 64, 16, 256, 8, 2, 0, 1>;    // protein conv1 (+emb), 256 thr
using CD1 = CC<4, 64, 16, 64, 8, 2, 0, 1>;     // drug conv1 (+emb)
using CP2 = CC<8, 40, 20, 256, 16, 4, 0, 0>;   // protein conv2
using CD2 = CC<6, 40, 20, 64, 16, 2, 0, 0>;    // drug conv2
using CP3 = CC<12, 80, 16, 128, 32, 4, 0, 0>;  // protein conv3
using CD3 = CC<8, 80, 16, 64, 32, 2, 0, 0>;    // drug conv3
using CPp = CC<1, 160, 32, 128, 32, 4, 1, 0>;  // protein proj
using CDp = CC<1, 160, 32, 64, 32, 2, 1, 0>;   // drug proj
using CPa = CC<1, 160, 32, 128, 32, 4, 2, 0>;  // protein att_out
using CDa = CC<1, 160, 32, 64, 32, 2, 2, 0>;   // drug att_out

// ---------------- launch ----------------
extern "C" void kernel_launch(void* const* d_in, const int* in_sizes, int n_in,
                              void* d_out, int out_size)
{
    const int*   dtok = (const int*)d_in[0];
    const int*   ptok = (const int*)d_in[1];
    const float* demb = (const float*)d_in[2];
    const float* pemb = (const float*)d_in[3];
    const float* dW1 = (const float*)d_in[4],  *db1 = (const float*)d_in[5];
    const float* dW2 = (const float*)d_in[6],  *db2 = (const float*)d_in[7];
    const float* dW3 = (const float*)d_in[8],  *db3 = (const float*)d_in[9];
    const float* pW1 = (const float*)d_in[10], *pb1 = (const float*)d_in[11];
    const float* pW2 = (const float*)d_in[12], *pb2 = (const float*)d_in[13];
    const float* pW3 = (const float*)d_in[14], *pb3 = (const float*)d_in[15];
    const float* dattW = (const float*)d_in[16], *dattb = (const float*)d_in[17];
    const float* pattW = (const float*)d_in[18], *pattb = (const float*)d_in[19];
    const float* attW  = (const float*)d_in[20], *attb  = (const float*)d_in[21];
    const float* fc1W = (const float*)d_in[22], *fc1b = (const float*)d_in[23];
    const float* fc2W = (const float*)d_in[24], *fc2b = (const float*)d_in[25];
    const float* fc3W = (const float*)d_in[26], *fc3b = (const float*)d_in[27];
    const float* outW = (const float*)d_in[28], *outb = (const float*)d_in[29];
    float* out = (float*)d_out;

    float *d1, *d2, *dc, *p1, *p2, *pc;
    float *datt, *patt, *Sd, *Sp, *catte, *patte, *pairv;
    cudaGetSymbolAddress((void**)&d1, g_d1);
    cudaGetSymbolAddress((void**)&d2, g_d2);
    cudaGetSymbolAddress((void**)&dc, g_dc);
    cudaGetSymbolAddress((void**)&p1, g_p1);
    cudaGetSymbolAddress((void**)&p2, g_p2);
    cudaGetSymbolAddress((void**)&pc, g_pc);
    cudaGetSymbolAddress((void**)&datt, g_datt);
    cudaGetSymbolAddress((void**)&patt, g_patt);
    cudaGetSymbolAddress((void**)&Sd, g_Sd);
    cudaGetSymbolAddress((void**)&Sp, g_Sp);
    cudaGetSymbolAddress((void**)&catte, g_catte);
    cudaGetSymbolAddress((void**)&patte, g_patte);
    cudaGetSymbolAddress((void**)&pairv, g_pair);

    // conv1 (protein: grid 5x5x16 = 400; drug: 1x5x16 = 80)
    dual_conv<CP1, CD1><<<400 + 80, 256>>>(
        pemb, ptok, pW1, pb1, p1, PLEN, P1L, 0.f, 5, 5,
        demb, dtok, dW1, db1, d1, DLEN, D1L, 0.f, 1, 5);

    // conv2 (protein 5x5x16 = 400; drug 1x5x16 = 80)
    dual_conv<CP2, CD2><<<400 + 80, 256>>>(
        p1, 0, pW2, pb2, p2, P1L, P2L, 0.f, 5, 5,
        d1, 0, dW2, db2, d2, D1L, D2L, 0.f, 1, 5);

    // conv3 (protein 10x5x16 = 800; drug 1x5x16 = 80)
    dual_conv<CP3, CD3><<<800 + 80, 256>>>(
        p2, 0, pW3, pb3, pc, P2L, P3L, 0.f, 10, 5,
        d2, 0, dW3, db3, dc, D2L, D3L, 0.f, 1, 5);

    // attention projections (protein 10x5x16 = 800; drug 1x5x16 = 80)
    dual_conv<CPp, CDp><<<800 + 80, 256>>>(
        pc, 0, pattW, pattb, patt, P3L, P3L, 0.f, 10, 5,
        dc, 0, dattW, dattb, datt, D3L, D3L, 0.f, 1, 5);

    // interaction sums
    interact_kernel<<<dim3(C3, NB), 256>>>(datt, patt, Sd, Sp);

    // attention outputs: sigmoid((S/N) @ attW^T + attb)
    dual_conv<CPa, CDa><<<800 + 80, 256>>>(
        Sp, 0, attW, attb, patte, P3L, P3L, 1.f / (float)D3L, 10, 5,
        Sd, 0, attW, attb, catte, D3L, D3L, 1.f / (float)P3L, 1, 5);

    // gated global max pool (drug rows zy<16, protein zy>=16)
    pool_dual<<<dim3(C3, 2 * NB), 32>>>(dc, catte, pc, patte, pairv);

    // MLP head
    mlp_kernel<<<NB, 1024>>>(pairv, fc1W, fc1b, fc2W, fc2b, fc3W, fc3b, outW, outb, out);
}